// round 9
// baseline (speedup 1.0000x reference)
#include <cuda_runtime.h>
#include <cstdint>

// ChebyshevEncoder fused kernel v6 for GB300 (sm_103a)
//
// 4-CTA cluster = one batch-row worker; CTA rank h owns head h.
// 1024 threads/CTA: thread t = (feature i = t>>1, k-half = t&1).
//
// v6 over v5:
//  - NO shfl in the hot loop: each thread STS.64s raw (sum,sq) to RED.
//  - wide stats phase: all 32 warps reduce RED (4 warps per row), one
//    5-level shfl per window (amortized), lane0 of every warp pushes its
//    partial float2 to all 4 CTAs via st.shared::cluster + release-arrive
//    on each CTA's mbarrier (128 arrivals). Replaces cluster_sync: no
//    CCTL.IVALL L1 flush, wait is mbarrier try_wait (acquire.cluster).
//  - epilogue(b-1) stays fused row-by-row into compute(b) (v5 pipeline).

#define TPB          1024
#define NUM_CLUSTERS 32
#define NBLK         (NUM_CLUSTERS * 4)
#define ROWS_ITER    8
#define NBATCH       (4096 / ROWS_ITER)          // 512 row-batches

// smem layout (floats; keep total <= 232,448 bytes)
#define SMEM_A       0                                 // [8][1024] float4 = 32768
#define SMEM_RED     (SMEM_A + ROWS_ITER * TPB * 4)    // [8][1024] float2 = 16384
#define SMEM_PAR     (SMEM_RED + ROWS_ITER * TPB * 2)  // [2][4][32] float2 = 512
#define SMEM_MR      (SMEM_PAR + 512)                  // 8 rows * float2 = 16
#define SMEM_MBAR    (SMEM_MR + 16)                    // 2 x b64 = 4 floats (8B aligned)
#define SMEM_G       (SMEM_MBAR + 4)                   // [1024] float4 = 4096
#define SMEM_B       (SMEM_G + TPB * 4)                // [1024] float4 = 4096
#define SMEM_FLOATS  (SMEM_B + TPB * 4)
#define SMEM_BYTES   (SMEM_FLOATS * 4)                 // 231,520 B

typedef unsigned long long ull;

__device__ __forceinline__ ull pack2(float lo, float hi) {
    ull r; asm("mov.b64 %0, {%1, %2};" : "=l"(r) : "f"(lo), "f"(hi)); return r;
}
__device__ __forceinline__ void unpack2(ull v, float& lo, float& hi) {
    asm("mov.b64 {%0, %1}, %2;" : "=f"(lo), "=f"(hi) : "l"(v));
}
__device__ __forceinline__ ull ffma2(ull a, ull b, ull c) {
    ull d; asm("fma.rn.f32x2 %0, %1, %2, %3;" : "=l"(d) : "l"(a), "l"(b), "l"(c)); return d;
}
__device__ __forceinline__ ull fadd2(ull a, ull b) {
    ull d; asm("add.rn.f32x2 %0, %1, %2;" : "=l"(d) : "l"(a), "l"(b)); return d;
}
__device__ __forceinline__ float tanhf_hw(float x) {
    float r; asm("tanh.approx.f32 %0, %1;" : "=f"(r) : "f"(x)); return r;
}
__device__ __forceinline__ uint32_t smem_u32(const void* p) {
    return (uint32_t)__cvta_generic_to_shared(p);
}
__device__ __forceinline__ uint32_t mapa_rank(uint32_t laddr, uint32_t rank) {
    uint32_t raddr;
    asm("mapa.shared::cluster.u32 %0, %1, %2;" : "=r"(raddr) : "r"(laddr), "r"(rank));
    return raddr;
}
__device__ __forceinline__ void st_remote_b64(uint32_t raddr, ull v) {
    asm volatile("st.shared::cluster.b64 [%0], %1;" :: "r"(raddr), "l"(v) : "memory");
}
__device__ __forceinline__ void mbar_arrive_remote(uint32_t raddr) {
    asm volatile("mbarrier.arrive.release.cluster.shared::cluster.b64 _, [%0];"
                 :: "r"(raddr) : "memory");
}
__device__ __forceinline__ void mbar_init(uint32_t laddr, uint32_t count) {
    asm volatile("mbarrier.init.shared.b64 [%0], %1;" :: "r"(laddr), "r"(count) : "memory");
}
__device__ __forceinline__ void mbar_wait_cluster(uint32_t laddr, uint32_t parity) {
    uint32_t done;
    asm volatile(
        "{\n\t.reg .pred p;\n\t"
        "mbarrier.try_wait.parity.acquire.cluster.shared::cta.b64 p, [%1], %2;\n\t"
        "selp.b32 %0, 1, 0, p;\n\t}"
        : "=r"(done) : "r"(laddr), "r"(parity) : "memory");
    if (!done) {
        asm volatile(
            "{\n\t.reg .pred P1;\n\t"
            "W_%=:\n\t"
            "mbarrier.try_wait.parity.acquire.cluster.shared::cta.b64 P1, [%0], %1, 0x989680;\n\t"
            "@P1 bra.uni D_%=;\n\t"
            "bra.uni W_%=;\n\t"
            "D_%=:\n\t}"
            :: "r"(laddr), "r"(parity) : "memory");
    }
}
__device__ __forceinline__ void cluster_sync() {
    asm volatile("barrier.cluster.arrive.aligned;" ::: "memory");
    asm volatile("barrier.cluster.wait.aligned;" ::: "memory");
}

__global__ void __launch_bounds__(TPB, 1) __cluster_dims__(4, 1, 1)
cheb_fused_kernel(const float* __restrict__ x,
                  const float* __restrict__ scale,
                  const float* __restrict__ poly,
                  const float* __restrict__ kern,
                  const float* __restrict__ gamma,
                  const float* __restrict__ beta,
                  float* __restrict__ out)
{
    extern __shared__ float sm[];
    const int tid   = threadIdx.x;
    const int lane  = tid & 31;
    const int wid   = tid >> 5;                   // 0..31
    const int feat  = tid >> 1;                   // feature within head
    const int khalf = tid & 1;                    // which 4 of the 8 k-cols
    uint32_t h;
    asm("mov.u32 %0, %%cluster_ctarank;" : "=r"(h));
    const int cid = blockIdx.x >> 2;

    // ---- one-time preload: folded half-row weights (f32x2 packed) + scale ----
    ull W2[8][2];
    const float sc = scale[feat];
    {
        const float4* kp = (const float4*)kern + ((size_t)h * 512 + feat) * 16 + khalf;
        const float4  pv = ((const float4*)poly)[((size_t)h * 512 + feat) * 2 + khalf];
        #pragma unroll
        for (int m = 0; m < 8; m++) {
            float4 a = kp[m * 2];
            W2[m][0] = pack2(a.x * pv.x, a.y * pv.y);
            W2[m][1] = pack2(a.z * pv.z, a.w * pv.w);
        }
    }
    // gamma/beta slices -> smem
    ((float4*)(sm + SMEM_G))[tid] = __ldg((const float4*)(gamma + (size_t)h * 4096) + tid);
    ((float4*)(sm + SMEM_B))[tid] = __ldg((const float4*)(beta  + (size_t)h * 4096) + tid);
    // mbarriers: one per window parity, 128 arrivals (32 warps x 4 src CTAs)
    if (tid == 0) {
        mbar_init(smem_u32(sm + SMEM_MBAR), 128);
        mbar_init(smem_u32(sm + SMEM_MBAR + 2), 128);
    }

    cluster_sync();  // peers launched + mbarriers initialized everywhere

    int ph0 = 0, ph1 = 0;          // mbarrier phase trackers per parity slot
    int prev_row0 = 0;
    const float invN = 1.0f / 16384.0f;

    // prefetch x for first row of first batch
    float xnext = x[(size_t)(cid * ROWS_ITER) * 512 + feat];

    #pragma unroll 1
    for (int it = 0; ; ++it) {
        const int batch = cid + it * NUM_CLUSTERS;
        const bool comp = (batch < NBATCH);
        const int row0 = batch * ROWS_ITER;

        float4* ap = (float4*)(sm + SMEM_A) + tid;
        float2* rp = (float2*)(sm + SMEM_RED) + tid;
        float4* op = (float4*)(out + (size_t)prev_row0 * 16384 + (size_t)h * 4096) + tid;

        // ---- fused loop: epilogue(prev batch) + compute(this batch) ----
        #pragma unroll 1
        for (int r = 0; r < ROWS_ITER; r++) {
            if (it > 0) {
                const float2 mr = ((const float2*)(sm + SMEM_MR))[r];
                const float4 va = *ap;
                const float4 gv  = ((const float4*)(sm + SMEM_G))[tid];
                const float4 bvv = ((const float4*)(sm + SMEM_B))[tid];
                float4 o;
                o.x = fmaf(fmaf(va.x, mr.x, mr.y), gv.x, bvv.x);
                o.y = fmaf(fmaf(va.y, mr.x, mr.y), gv.y, bvv.y);
                o.z = fmaf(fmaf(va.z, mr.x, mr.y), gv.z, bvv.z);
                o.w = fmaf(fmaf(va.w, mr.x, mr.y), gv.w, bvv.w);
                __stcs(op, o);
                op += 4096;
            }
            if (comp) {
                const float xv = xnext;
                {
                    int nb = batch + NUM_CLUSTERS;
                    int nrow = (r < ROWS_ITER - 1) ? (row0 + r + 1)
                             : ((nb < NBATCH) ? nb * ROWS_ITER : row0);
                    xnext = x[(size_t)nrow * 512 + feat];
                }

                const float xs = xv * sc;
                ull t2[7];
                {
                    const float x2 = xs + xs;
                    float tm2 = 1.0f, tm1 = xs;
                    t2[0] = pack2(xs, xs);
                    #pragma unroll
                    for (int m = 2; m < 8; m++) {
                        const float T = fmaf(x2, tm1, -tm2);
                        tm2 = tm1; tm1 = T;
                        t2[m - 1] = pack2(T, T);
                    }
                }
                ull acc0 = W2[0][0], acc1 = W2[0][1];
                #pragma unroll
                for (int m = 0; m < 7; m++) {
                    acc0 = ffma2(t2[m], W2[m + 1][0], acc0);
                    acc1 = ffma2(t2[m], W2[m + 1][1], acc1);
                }

                float a0, a1, a2, a3;
                unpack2(acc0, a0, a1);
                unpack2(acc1, a2, a3);
                const float b0 = 0.5f * a0, b1 = 0.5f * a1;
                const float b2 = 0.5f * a2, b3 = 0.5f * a3;
                const float v0 = fmaf(tanhf_hw(b0), b0, b0);
                const float v1 = fmaf(tanhf_hw(b1), b1, b1);
                const float v2 = fmaf(tanhf_hw(b2), b2, b2);
                const float v3 = fmaf(tanhf_hw(b3), b3, b3);

                const float sum = (v0 + v1) + (v2 + v3);
                const float sq  = fmaf(v0, v0, fmaf(v1, v1, fmaf(v2, v2, v3 * v3)));

                *ap = make_float4(v0, v1, v2, v3);   // overwrite own slot (safe)
                *rp = make_float2(sum, sq);          // raw per-thread stats
                rp += TPB;
            }
            ap += TPB;
        }

        if (!comp) break;   // drain window flushed last epilogue; done
        __syncthreads();    // RED + acts complete

        const int p = it & 1;
        const uint32_t mb_l = smem_u32(sm + SMEM_MBAR + 2 * p);

        // ---- wide stats: 4 warps per row reduce 1024 (sum,sq) pairs ----
        {
            const int row = wid >> 2;                       // 0..7
            const int j   = ((wid & 3) << 5) | lane;        // 0..127
            const ull* sp = (const ull*)(sm + SMEM_RED) + row * TPB + j;
            ull s2 = sp[0];
            #pragma unroll
            for (int q = 1; q < 8; q++) s2 = fadd2(s2, sp[q * 128]);
            float s, q;
            unpack2(s2, s, q);
            #pragma unroll
            for (int o = 16; o > 0; o >>= 1) {
                s += __shfl_xor_sync(0xffffffffu, s, o);
                q += __shfl_xor_sync(0xffffffffu, q, o);
            }
            if (lane == 0) {
                // push partial to PAR[p][h][wid] on every CTA, then arrive
                const ull v = pack2(s, q);
                const uint32_t laddr =
                    smem_u32((float2*)(sm + SMEM_PAR) + (p * 128 + (int)h * 32 + wid));
                #pragma unroll
                for (uint32_t dst = 0; dst < 4; dst++)
                    st_remote_b64(mapa_rank(laddr, dst), v);
                #pragma unroll
                for (uint32_t dst = 0; dst < 4; dst++)
                    mbar_arrive_remote(mapa_rank(mb_l, dst));
            }
        }

        // ---- mr-phase: 8 threads wait all 128 arrivals, compute mean/rstd ----
        if (tid < 8) {
            mbar_wait_cluster(mb_l, p ? ph1 : ph0);
            const float2* par = (const float2*)(sm + SMEM_PAR) + p * 128;
            float s = 0.f, q = 0.f;
            #pragma unroll
            for (int rk = 0; rk < 4; rk++)
                #pragma unroll
                for (int sb = 0; sb < 4; sb++) {
                    const float2 v = par[rk * 32 + 4 * tid + sb];
                    s += v.x; q += v.y;
                }
            const float mean = s * invN;
            const float var  = fmaf(-mean, mean, q * invN);
            const float rstd = rsqrtf(var + 1e-5f);
            ((float2*)(sm + SMEM_MR))[tid] = make_float2(rstd, -mean * rstd);
        }
        if (p) ph1 ^= 1; else ph0 ^= 1;
        __syncthreads();    // mr visible; bounds warp skew for RED/PAR reuse

        prev_row0 = row0;
    }
}

extern "C" void kernel_launch(void* const* d_in, const int* in_sizes, int n_in,
                              void* d_out, int out_size)
{
    const float* x     = (const float*)d_in[0];   // [4096, 512]
    const float* scale = (const float*)d_in[1];   // [512]
    const float* poly  = (const float*)d_in[2];   // [4, 512, 8]
    const float* kern  = (const float*)d_in[3];   // [4, 512, 8, 8]
    const float* gamma = (const float*)d_in[4];   // [16384]
    const float* beta  = (const float*)d_in[5];   // [16384]
    float* out = (float*)d_out;                   // [4096, 16384]

    (void)in_sizes; (void)n_in; (void)out_size;

    cudaFuncSetAttribute(cheb_fused_kernel,
                         cudaFuncAttributeMaxDynamicSharedMemorySize, SMEM_BYTES);

    cheb_fused_kernel<<<NBLK, TPB, SMEM_BYTES, 0>>>(x, scale, poly, kern, gamma, beta, out);
}

// round 10
// speedup vs baseline: 1.1306x; 1.1306x over previous
#include <cuda_runtime.h>
#include <cstdint>

// ChebyshevEncoder fused kernel v7 for GB300 (sm_103a)
//
// Base = v5 (best, 106.8us): 4-CTA cluster per row-batch, 1024 thr/CTA,
// thread t=(feat=t>>1, khalf=t&1), 16 weight regs, fused epilogue(b-1)
// into compute(b), in-loop warp shfl for LN stats.
//
// v7 deltas:
//  - shfl reduction on packed (sum,sq): 2 SHFL + 1 add.f32x2 per level.
//  - lane0 stores warp partial to RED[r][wid] (transposed, conflict-free).
//  - CTA-partial phase is 8-warp-wide butterfly (was 16-thread serial x32
//    LDS); lane0 pushes one b64 CTA total to all 4 CTAs (32B DSMEM).
//  - mean/rstd stored pre-duplicated (rstd,rstd)/(off,off); epilogue does
//    4 fma.rn.f32x2 with v2.u64 shared loads + st.global.cs.v2.u64.
//  - silu pre-scale via mul.rn.f32x2. One fewer __syncthreads per window.

#define TPB          1024
#define NUM_CLUSTERS 32
#define NBLK         (NUM_CLUSTERS * 4)
#define ROWS_ITER    8
#define NBATCH       (4096 / ROWS_ITER)          // 512 row-batches

// smem layout (floats)
#define SMEM_A       0                                 // [8][1024] float4 = 32768
#define SMEM_RED     (SMEM_A + ROWS_ITER * TPB * 4)    // [8 rows][32 warps] float2 = 512
#define SMEM_PAR     (SMEM_RED + 512)                  // [2][8 rows][4 ranks] float2 = 128
#define SMEM_MRS     (SMEM_PAR + 128)                  // 8 x float2 (rstd,rstd) = 16
#define SMEM_MRO     (SMEM_MRS + 16)                   // 8 x float2 (off,off) = 16
#define SMEM_G       (SMEM_MRO + 16)                   // [1024] float4 = 4096
#define SMEM_B       (SMEM_G + TPB * 4)                // [1024] float4 = 4096
#define SMEM_FLOATS  (SMEM_B + TPB * 4)
#define SMEM_BYTES   (SMEM_FLOATS * 4)                 // 166,560 B

typedef unsigned long long ull;

__device__ __forceinline__ ull pack2(float lo, float hi) {
    ull r; asm("mov.b64 %0, {%1, %2};" : "=l"(r) : "f"(lo), "f"(hi)); return r;
}
__device__ __forceinline__ void unpack2(ull v, float& lo, float& hi) {
    asm("mov.b64 {%0, %1}, %2;" : "=f"(lo), "=f"(hi) : "l"(v));
}
__device__ __forceinline__ ull ffma2(ull a, ull b, ull c) {
    ull d; asm("fma.rn.f32x2 %0, %1, %2, %3;" : "=l"(d) : "l"(a), "l"(b), "l"(c)); return d;
}
__device__ __forceinline__ ull fadd2(ull a, ull b) {
    ull d; asm("add.rn.f32x2 %0, %1, %2;" : "=l"(d) : "l"(a), "l"(b)); return d;
}
__device__ __forceinline__ ull fmul2(ull a, ull b) {
    ull d; asm("mul.rn.f32x2 %0, %1, %2;" : "=l"(d) : "l"(a), "l"(b)); return d;
}
// butterfly xor-shfl of a packed f32 pair (2 x shfl.b32, halves independent)
__device__ __forceinline__ ull shfl_xor_b64(ull v, int o) {
    float lo, hi;
    unpack2(v, lo, hi);
    float lo2, hi2;
    asm("shfl.sync.bfly.b32 %0, %1, %2, 0x1F, 0xFFFFFFFF;" : "=f"(lo2) : "f"(lo), "r"(o));
    asm("shfl.sync.bfly.b32 %0, %1, %2, 0x1F, 0xFFFFFFFF;" : "=f"(hi2) : "f"(hi), "r"(o));
    return pack2(lo2, hi2);
}
__device__ __forceinline__ float tanhf_hw(float x) {
    float r; asm("tanh.approx.f32 %0, %1;" : "=f"(r) : "f"(x)); return r;
}
__device__ __forceinline__ uint32_t smem_u32(const void* p) {
    return (uint32_t)__cvta_generic_to_shared(p);
}
__device__ __forceinline__ uint32_t mapa_rank(uint32_t laddr, uint32_t rank) {
    uint32_t raddr;
    asm("mapa.shared::cluster.u32 %0, %1, %2;" : "=r"(raddr) : "r"(laddr), "r"(rank));
    return raddr;
}
__device__ __forceinline__ void st_remote_b64(uint32_t raddr, ull v) {
    asm volatile("st.shared::cluster.b64 [%0], %1;" :: "r"(raddr), "l"(v) : "memory");
}
__device__ __forceinline__ void lds_v2u64(uint32_t addr, ull& a, ull& b) {
    asm("ld.shared.v2.u64 {%0, %1}, [%2];" : "=l"(a), "=l"(b) : "r"(addr));
}
__device__ __forceinline__ void stg_cs_v2u64(void* p, ull a, ull b) {
    asm volatile("st.global.cs.v2.u64 [%0], {%1, %2};" :: "l"(p), "l"(a), "l"(b) : "memory");
}
__device__ __forceinline__ void cluster_sync() {
    asm volatile("barrier.cluster.arrive.aligned;" ::: "memory");
    asm volatile("barrier.cluster.wait.aligned;" ::: "memory");
}

__global__ void __launch_bounds__(TPB, 1) __cluster_dims__(4, 1, 1)
cheb_fused_kernel(const float* __restrict__ x,
                  const float* __restrict__ scale,
                  const float* __restrict__ poly,
                  const float* __restrict__ kern,
                  const float* __restrict__ gamma,
                  const float* __restrict__ beta,
                  float* __restrict__ out)
{
    extern __shared__ float sm[];
    const int tid   = threadIdx.x;
    const int lane  = tid & 31;
    const int wid   = tid >> 5;                   // 0..31
    const int feat  = tid >> 1;                   // feature within head
    const int khalf = tid & 1;                    // which 4 of the 8 k-cols
    uint32_t h;
    asm("mov.u32 %0, %%cluster_ctarank;" : "=r"(h));
    const int cid = blockIdx.x >> 2;

    // ---- one-time preload: folded half-row weights (f32x2 packed) + scale ----
    ull W2[8][2];
    const float sc = scale[feat];
    {
        const float4* kp = (const float4*)kern + ((size_t)h * 512 + feat) * 16 + khalf;
        const float4  pv = ((const float4*)poly)[((size_t)h * 512 + feat) * 2 + khalf];
        #pragma unroll
        for (int m = 0; m < 8; m++) {
            float4 a = kp[m * 2];
            W2[m][0] = pack2(a.x * pv.x, a.y * pv.y);
            W2[m][1] = pack2(a.z * pv.z, a.w * pv.w);
        }
    }
    // gamma/beta slices -> smem (read per row via LDS, keeps regs <= 64)
    ((float4*)(sm + SMEM_G))[tid] = __ldg((const float4*)(gamma + (size_t)h * 4096) + tid);
    ((float4*)(sm + SMEM_B))[tid] = __ldg((const float4*)(beta  + (size_t)h * 4096) + tid);

    cluster_sync();  // peers launched; DSMEM slots safe to target

    int prev_row0 = 0;
    const float invN = 1.0f / 16384.0f;
    const ull half2 = pack2(0.5f, 0.5f);

    // smem addresses for packed epilogue loads
    const uint32_t gaddr = smem_u32((const float4*)(sm + SMEM_G) + tid);
    const uint32_t baddr = smem_u32((const float4*)(sm + SMEM_B) + tid);

    // prefetch x for first row of first batch
    float xnext = x[(size_t)(cid * ROWS_ITER) * 512 + feat];

    #pragma unroll 1
    for (int it = 0; ; ++it) {
        const int batch = cid + it * NUM_CLUSTERS;
        const bool comp = (batch < NBATCH);
        const int row0 = batch * ROWS_ITER;
        const int p = it & 1;

        float4* ap = (float4*)(sm + SMEM_A) + tid;
        float4* op = (float4*)(out + (size_t)prev_row0 * 16384 + (size_t)h * 4096) + tid;

        // ---- fused loop: epilogue(prev batch) + compute(this batch) ----
        #pragma unroll 1
        for (int r = 0; r < ROWS_ITER; r++) {
            if (it > 0) {
                const ull mrs = ((const ull*)(sm + SMEM_MRS))[r];   // (rstd,rstd)
                const ull mro = ((const ull*)(sm + SMEM_MRO))[r];   // (off,off)
                ull va0, va1, gv0, gv1, bv0, bv1;
                lds_v2u64(smem_u32(ap), va0, va1);
                lds_v2u64(gaddr, gv0, gv1);
                lds_v2u64(baddr, bv0, bv1);
                const ull o0 = ffma2(ffma2(va0, mrs, mro), gv0, bv0);
                const ull o1 = ffma2(ffma2(va1, mrs, mro), gv1, bv1);
                stg_cs_v2u64(op, o0, o1);
                op += 4096;
            }
            if (comp) {
                const float xv = xnext;
                {
                    int nb = batch + NUM_CLUSTERS;
                    int nrow = (r < ROWS_ITER - 1) ? (row0 + r + 1)
                             : ((nb < NBATCH) ? nb * ROWS_ITER : row0);
                    xnext = x[(size_t)nrow * 512 + feat];
                }

                const float xs = xv * sc;
                ull t2[7];
                {
                    const float x2 = xs + xs;
                    float tm2 = 1.0f, tm1 = xs;
                    t2[0] = pack2(xs, xs);
                    #pragma unroll
                    for (int m = 2; m < 8; m++) {
                        const float T = fmaf(x2, tm1, -tm2);
                        tm2 = tm1; tm1 = T;
                        t2[m - 1] = pack2(T, T);
                    }
                }
                ull acc0 = W2[0][0], acc1 = W2[0][1];
                #pragma unroll
                for (int m = 0; m < 7; m++) {
                    acc0 = ffma2(t2[m], W2[m + 1][0], acc0);
                    acc1 = ffma2(t2[m], W2[m + 1][1], acc1);
                }

                // silu via tanh: v = b*(1+tanh(b)), b = a/2 (pre-scale packed)
                const ull bb0 = fmul2(acc0, half2);
                const ull bb1 = fmul2(acc1, half2);
                float b0, b1, b2, b3;
                unpack2(bb0, b0, b1);
                unpack2(bb1, b2, b3);
                const float v0 = fmaf(tanhf_hw(b0), b0, b0);
                const float v1 = fmaf(tanhf_hw(b1), b1, b1);
                const float v2 = fmaf(tanhf_hw(b2), b2, b2);
                const float v3 = fmaf(tanhf_hw(b3), b3, b3);

                const float sum = (v0 + v1) + (v2 + v3);
                const float sq  = fmaf(v0, v0, fmaf(v1, v1, fmaf(v2, v2, v3 * v3)));

                *ap = make_float4(v0, v1, v2, v3);   // overwrite own slot (safe)

                // packed warp reduction of (sum, sq): 2 SHFL + 1 ADD2 / level
                ull ps = pack2(sum, sq);
                #pragma unroll
                for (int o = 16; o > 0; o >>= 1)
                    ps = fadd2(ps, shfl_xor_b64(ps, o));
                if (lane == 0)
                    ((ull*)(sm + SMEM_RED))[r * 32 + wid] = ps;   // RED[r][wid]
            }
            ap += TPB;
        }

        if (!comp) break;   // drain window flushed last epilogue; done
        __syncthreads();    // RED complete

        // ---- wide CTA-partial: warp w reduces row w across 32 warps ----
        if (wid < 8) {
            ull v = ((const ull*)(sm + SMEM_RED))[wid * 32 + lane];  // conflict-free
            #pragma unroll
            for (int o = 16; o > 0; o >>= 1)
                v = fadd2(v, shfl_xor_b64(v, o));
            if (lane == 0) {
                // push CTA total for row wid to PAR[p][wid][h] on all 4 CTAs
                const uint32_t laddr =
                    smem_u32((ull*)(sm + SMEM_PAR) + (p * 32 + wid * 4 + (int)h));
                #pragma unroll
                for (uint32_t dst = 0; dst < 4; dst++)
                    st_remote_b64(mapa_rank(laddr, dst), v);
            }
        }
        cluster_sync();   // release our pushes / acquire peers' (no race: PAR x2 parity)

        // ---- finish: 8 lane0s combine 4 rank totals, emit mean/rstd ----
        if (wid < 8 && lane == 0) {
            const ull* pr = (const ull*)(sm + SMEM_PAR) + p * 32 + wid * 4;
            const ull t = fadd2(fadd2(pr[0], pr[1]), fadd2(pr[2], pr[3]));
            float s, q;
            unpack2(t, s, q);
            const float mean = s * invN;
            const float var  = fmaf(-mean, mean, q * invN);
            const float rstd = rsqrtf(var + 1e-5f);
            const float off  = -mean * rstd;
            ((ull*)(sm + SMEM_MRS))[wid] = pack2(rstd, rstd);
            ((ull*)(sm + SMEM_MRO))[wid] = pack2(off, off);
        }
        __syncthreads();    // MRS/MRO visible before next window's epilogue

        prev_row0 = row0;
    }
}

extern "C" void kernel_launch(void* const* d_in, const int* in_sizes, int n_in,
                              void* d_out, int out_size)
{
    const float* x     = (const float*)d_in[0];   // [4096, 512]
    const float* scale = (const float*)d_in[1];   // [512]
    const float* poly  = (const float*)d_in[2];   // [4, 512, 8]
    const float* kern  = (const float*)d_in[3];   // [4, 512, 8, 8]
    const float* gamma = (const float*)d_in[4];   // [16384]
    const float* beta  = (const float*)d_in[5];   // [16384]
    float* out = (float*)d_out;                   // [4096, 16384]

    (void)in_sizes; (void)n_in; (void)out_size;

    cudaFuncSetAttribute(cheb_fused_kernel,
                         cudaFuncAttributeMaxDynamicSharedMemorySize, SMEM_BYTES);

    cheb_fused_kernel<<<NBLK, TPB, SMEM_BYTES, 0>>>(x, scale, poly, kern, gamma, beta, out);
}